// round 14
// baseline (speedup 1.0000x reference)
#include <cuda_runtime.h>
#include <cuda_fp16.h>
#include <cstdint>

// ---------------------------------------------------------------------------
// LeWinAttention round 14: R13 + 6-stage GEMM pipeline + attention split-wait
// (q/k group waited before scores, v group waited only before P.V).
// ---------------------------------------------------------------------------

__device__ __half g_xh[134217728];    // x fp16          (256 MB)
__device__ __half g_qkvh[402653184];  // qkv fp16        (768 MB)
__device__ __half g_aouth[134217728]; // attn out fp16   (256 MB)
__device__ __half g_wh[262144];       // qkv_w + proj_w
__device__ __half g_biash[32768];     // bias [8][64][64] fp16

// ---------------- helpers --------------------------------------------------
__device__ __forceinline__ void mma_f16(float* d, const unsigned* a, const unsigned* b) {
    asm volatile(
        "mma.sync.aligned.m16n8k16.row.col.f32.f16.f16.f32 "
        "{%0,%1,%2,%3}, {%4,%5,%6,%7}, {%8,%9}, {%0,%1,%2,%3};"
        : "+f"(d[0]), "+f"(d[1]), "+f"(d[2]), "+f"(d[3])
        : "r"(a[0]), "r"(a[1]), "r"(a[2]), "r"(a[3]), "r"(b[0]), "r"(b[1]));
}
__device__ __forceinline__ void ldsm4(unsigned& r0, unsigned& r1, unsigned& r2,
                                      unsigned& r3, uint32_t addr) {
    asm volatile("ldmatrix.sync.aligned.m8n8.x4.shared.b16 {%0,%1,%2,%3}, [%4];"
                 : "=r"(r0), "=r"(r1), "=r"(r2), "=r"(r3) : "r"(addr));
}
__device__ __forceinline__ void ldsm4t(unsigned& r0, unsigned& r1, unsigned& r2,
                                       unsigned& r3, uint32_t addr) {
    asm volatile("ldmatrix.sync.aligned.m8n8.x4.trans.shared.b16 {%0,%1,%2,%3}, [%4];"
                 : "=r"(r0), "=r"(r1), "=r"(r2), "=r"(r3) : "r"(addr));
}
__device__ __forceinline__ void cpasync16(uint32_t dst, const void* src) {
    asm volatile("cp.async.cg.shared.global [%0], [%1], 16;" :: "r"(dst), "l"(src));
}
#define CP_COMMIT() asm volatile("cp.async.commit_group;" ::: "memory")
#define CP_WAIT4()  asm volatile("cp.async.wait_group 4;" ::: "memory")
#define CP_WAIT1()  asm volatile("cp.async.wait_group 1;" ::: "memory")
#define CP_WAIT0()  asm volatile("cp.async.wait_group 0;" ::: "memory")

__device__ __forceinline__ void store2(float* p, float v0, float v1) {
    *(float2*)p = make_float2(v0, v1);
}
__device__ __forceinline__ void store2(__half* p, float v0, float v1) {
    *(__half2*)p = __floats2half2_rn(v0, v1);
}
__device__ __forceinline__ unsigned pack2(float x, float y) {
    __half2 h = __floats2half2_rn(x, y);
    return *(unsigned*)&h;
}

// FMA-pipe exp (no MUFU): exp(x) for x <= 0. rel err ~2e-6.
__device__ __forceinline__ float fexp(float x) {
    float y = fmaxf(x * 1.4426950408889634f, -126.0f);
    float r = y + 12582912.0f;
    float k = r - 12582912.0f;
    float f = y - k;
    float p = 0.0013333558f;
    p = fmaf(p, f, 0.0096181291f);
    p = fmaf(p, f, 0.0555041087f);
    p = fmaf(p, f, 0.2402264676f);
    p = fmaf(p, f, 0.6931471806f);
    p = fmaf(p, f, 1.0f);
    return __int_as_float(__float_as_int(p) + (((int)k) << 23));
}

// ---------------------------------------------------------------------------
__global__ void f2h_kernel(const float* __restrict__ in, __half* __restrict__ out, int n4)
{
    for (int i = blockIdx.x * blockDim.x + threadIdx.x; i < n4;
         i += gridDim.x * blockDim.x) {
        float4 v = *(const float4*)(in + (size_t)i * 4);
        __half2 h0 = __floats2half2_rn(v.x, v.y);
        __half2 h1 = __floats2half2_rn(v.z, v.w);
        uint2 u;
        u.x = *(unsigned*)&h0; u.y = *(unsigned*)&h1;
        *(uint2*)(out + (size_t)i * 4) = u;
    }
}

__global__ void bias_pre_kernel(const float* __restrict__ table,
                                const int* __restrict__ rpi,
                                __half* __restrict__ biash)
{
    int i = blockIdx.x * 256 + threadIdx.x;
    if (i < 4096) {
        int idx = rpi[i];
#pragma unroll
        for (int h = 0; h < 8; h++)
            biash[h * 4096 + i] = __float2half(table[idx * 8 + h]);
    }
}

// ---------------------------------------------------------------------------
// GEMM: CTA 128x128, warp tile 32x64, cp.async 6 stages (5 in flight).
// Stage: A[128][32h] 8KB + B[128][32h] 8KB = 16KB. smem 96 KB, 2 CTAs/SM.
// ---------------------------------------------------------------------------
#define GA_BYTES 8192
#define GSTAGE_B 16384
#define GNSTAGE  6

template <typename OutT>
__global__ void __launch_bounds__(256, 2)
gemm_cp_kernel(const __half* __restrict__ A, const __half* __restrict__ W,
               const float* __restrict__ bias, OutT* __restrict__ C, int Nc)
{
    extern __shared__ char sm[];
    uint32_t sbase;
    asm("{ .reg .u64 t; cvta.to.shared.u64 t, %1; cvt.u32.u64 %0, t; }"
        : "=r"(sbase) : "l"(sm));

    const int t    = threadIdx.x;
    const int lane = t & 31;
    const int gid  = lane >> 2;
    const int tig  = lane & 3;
    const int w    = t >> 5;
    const int wm   = w & 3;
    const int wn   = w >> 2;
    const size_t mBase = (size_t)blockIdx.y * 128;
    const int    nBase = blockIdx.x * 128;

    const int r0c = t >> 2;
    const int cc  = t & 3;
    const int csw0 = (cc ^ ((r0c >> 1) & 3)) << 4;
    const __half* aS0 = A + (mBase + r0c) * 256 + cc * 8;
    const __half* aS1 = A + (mBase + 64 + r0c) * 256 + cc * 8;
    const __half* bS0 = W + ((size_t)nBase + r0c) * 256 + cc * 8;
    const __half* bS1 = W + ((size_t)nBase + 64 + r0c) * 256 + cc * 8;
    const uint32_t dA0 = sbase + r0c * 64 + csw0;
    const uint32_t dA1 = sbase + (64 + r0c) * 64 + csw0;
    const uint32_t dB0 = sbase + GA_BYTES + r0c * 64 + csw0;
    const uint32_t dB1 = sbase + GA_BYTES + (64 + r0c) * 64 + csw0;

    uint32_t aAddr[2], bAddr[4];
#pragma unroll
    for (int mt = 0; mt < 2; mt++) {
        int row = wm * 32 + mt * 16 + ((lane >> 3) & 1) * 8 + (lane & 7);
        aAddr[mt] = sbase + row * 64 + ((((lane >> 4) ^ ((row >> 1) & 3))) << 4);
    }
#pragma unroll
    for (int q = 0; q < 4; q++) {
        int n = wn * 64 + q * 16 + ((lane >> 4) << 3) + (lane & 7);
        bAddr[q] = sbase + GA_BYTES + n * 64
                 + ((((lane >> 3) & 1) ^ ((n >> 1) & 3)) << 4);
    }

    float acc[2][8][4];
#pragma unroll
    for (int mt = 0; mt < 2; mt++)
#pragma unroll
        for (int nt = 0; nt < 8; nt++)
#pragma unroll
            for (int i = 0; i < 4; i++) acc[mt][nt][i] = 0.f;

    auto issue = [&](int s) {
        const int k0 = s << 5;
        const uint32_t so = (uint32_t)(s % GNSTAGE) * GSTAGE_B;
        cpasync16(dA0 + so, aS0 + k0);
        cpasync16(dA1 + so, aS1 + k0);
        cpasync16(dB0 + so, bS0 + k0);
        cpasync16(dB1 + so, bS1 + k0);
    };

    // prologue: 5 stages in flight
    issue(0); CP_COMMIT();
    issue(1); CP_COMMIT();
    issue(2); CP_COMMIT();
    issue(3); CP_COMMIT();
    issue(4); CP_COMMIT();

#pragma unroll
    for (int it = 0; it < 8; it++) {
        CP_WAIT4();          // stage it landed (<=4 younger groups pending)
        __syncthreads();

        const uint32_t so = (uint32_t)(it % GNSTAGE) * GSTAGE_B;
#pragma unroll
        for (int kk = 0; kk < 2; kk++) {
            const uint32_t kx = kk << 5;
            unsigned af[2][4], bf[8][2];
#pragma unroll
            for (int mt = 0; mt < 2; mt++)
                ldsm4(af[mt][0], af[mt][1], af[mt][2], af[mt][3],
                      (aAddr[mt] + so) ^ kx);
#pragma unroll
            for (int q = 0; q < 4; q++)
                ldsm4(bf[2 * q][0], bf[2 * q][1], bf[2 * q + 1][0], bf[2 * q + 1][1],
                      (bAddr[q] + so) ^ kx);
#pragma unroll
            for (int mt = 0; mt < 2; mt++)
#pragma unroll
                for (int nt = 0; nt < 8; nt++)
                    mma_f16(acc[mt][nt], af[mt], bf[nt]);
        }

        if (it + 5 < 8) issue(it + 5);
        CP_COMMIT();         // one group per iter keeps wait counting exact
    }

#pragma unroll
    for (int mt = 0; mt < 2; mt++) {
#pragma unroll
        for (int nt = 0; nt < 8; nt++) {
            int col = nBase + wn * 64 + nt * 8 + (tig << 1);
            float b0 = bias[col], b1 = bias[col + 1];
            size_t r0 = mBase + wm * 32 + mt * 16 + gid;
            store2(C + r0 * Nc + col, acc[mt][nt][0] + b0, acc[mt][nt][1] + b1);
            store2(C + (r0 + 8) * Nc + col, acc[mt][nt][2] + b0, acc[mt][nt][3] + b1);
        }
    }
}

// ---------------------------------------------------------------------------
// Tensor-core attention: 1 CTA per window, warp = head.
// Loads split: group0 = q+k chunks, group1 = v chunks; scores for half 0
// overlap the in-flight v transfer.
// ---------------------------------------------------------------------------
__global__ void __launch_bounds__(256)
attn_mma_kernel(const __half* __restrict__ qkv, const __half* __restrict__ biash,
                __half* __restrict__ aout)
{
    extern __shared__ char sm[];
    uint32_t sbase;
    asm("{ .reg .u64 t; cvta.to.shared.u64 t, %1; cvt.u32.u64 %0, t; }"
        : "=r"(sbase) : "l"(sm));

    const int b    = blockIdx.x;
    const int t    = threadIdx.x;
    const int lane = t & 31;
    const int h    = t >> 5;
    const int gid  = lane >> 2;
    const int tig  = lane & 3;

    // ---- load window qkv: q+k chunks (cc<64) in group 0, v chunks in group 1
    {
        const int r = t >> 2;
        const __half* src = qkv + ((size_t)b * 64 + r) * 768 + (t & 3) * 8;
        const uint32_t drow = sbase + r * 1536;
        const int rx = r & 7;
#pragma unroll
        for (int i = 0; i < 16; i++) {         // cc = (t&3)+4i in [0,64): q + k
            int cc = (t & 3) + (i << 2);
            cpasync16(drow + ((cc ^ rx) << 4), src + (i << 5));
        }
        CP_COMMIT();                           // group 0: q + k
#pragma unroll
        for (int i = 16; i < 24; i++) {        // cc in [64,96): v
            int cc = (t & 3) + (i << 2);
            cpasync16(drow + ((cc ^ rx) << 4), src + (i << 5));
        }
        CP_COMMIT();                           // group 1: v
    }
    CP_WAIT1();                                // q,k landed (v may be in flight)
    __syncthreads();

    uint32_t qA, kB, vB;
    {
        int r = ((lane >> 3) & 1) * 8 + (lane & 7);
        int ck = (h << 2) | (lane >> 4);
        qA = sbase + r * 1536 + ((ck ^ (r & 7)) << 4);
    }
    {
        int r = ((lane >> 4) << 3) + (lane & 7);
        int ck = ((8 + h) << 2) | ((lane >> 3) & 1);
        kB = sbase + r * 1536 + ((ck ^ (r & 7)) << 4);
    }
    {
        int tt = lane >> 3;
        int r = (tt & 1) * 8 + (lane & 7);
        int ck = ((16 + h) << 2) | (tt >> 1);
        vB = sbase + r * 1536 + ((ck ^ (r & 7)) << 4);
    }

    const float scale = 0.17677669529663687f;
    const __half* bia = biash + h * 4096;

#pragma unroll
    for (int h2 = 0; h2 < 2; h2++) {
        const int mt0 = h2 * 2;

        float sc[2][8][4];
#pragma unroll
        for (int mt = 0; mt < 2; mt++)
#pragma unroll
            for (int nt = 0; nt < 8; nt++)
#pragma unroll
                for (int i = 0; i < 4; i++) sc[mt][nt][i] = 0.f;

        unsigned kf[8][2][2];
#pragma unroll
        for (int ks = 0; ks < 2; ks++)
#pragma unroll
            for (int q = 0; q < 4; q++)
                ldsm4(kf[2 * q][ks][0], kf[2 * q][ks][1],
                      kf[2 * q + 1][ks][0], kf[2 * q + 1][ks][1],
                      (kB + q * 24576) ^ (ks << 5));
#pragma unroll
        for (int mt = 0; mt < 2; mt++)
#pragma unroll
            for (int ks = 0; ks < 2; ks++) {
                unsigned af[4];
                ldsm4(af[0], af[1], af[2], af[3],
                      (qA + (mt0 + mt) * 24576) ^ (ks << 5));
#pragma unroll
                for (int nt = 0; nt < 8; nt++)
                    mma_f16(sc[mt][nt], af, kf[nt][ks]);
            }

        float mx0[2], mx1[2];
#pragma unroll
        for (int mt = 0; mt < 2; mt++) {
            float m0 = -1e30f, m1 = -1e30f;
            int row = (mt0 + mt) * 16 + gid;
#pragma unroll
            for (int nt = 0; nt < 8; nt++) {
                float2 b0 = __half22float2(*(const __half2*)(bia + row * 64 + nt * 8 + 2 * tig));
                float2 b1 = __half22float2(*(const __half2*)(bia + (row + 8) * 64 + nt * 8 + 2 * tig));
                sc[mt][nt][0] = fmaf(sc[mt][nt][0], scale, b0.x);
                sc[mt][nt][1] = fmaf(sc[mt][nt][1], scale, b0.y);
                sc[mt][nt][2] = fmaf(sc[mt][nt][2], scale, b1.x);
                sc[mt][nt][3] = fmaf(sc[mt][nt][3], scale, b1.y);
                m0 = fmaxf(m0, fmaxf(sc[mt][nt][0], sc[mt][nt][1]));
                m1 = fmaxf(m1, fmaxf(sc[mt][nt][2], sc[mt][nt][3]));
            }
            m0 = fmaxf(m0, __shfl_xor_sync(0xffffffffu, m0, 1));
            m0 = fmaxf(m0, __shfl_xor_sync(0xffffffffu, m0, 2));
            m1 = fmaxf(m1, __shfl_xor_sync(0xffffffffu, m1, 1));
            m1 = fmaxf(m1, __shfl_xor_sync(0xffffffffu, m1, 2));
            mx0[mt] = m0; mx1[mt] = m1;
        }

        float s0[2], s1[2];
#pragma unroll
        for (int mt = 0; mt < 2; mt++) {
            float a0 = 0.f, a1 = 0.f;
#pragma unroll
            for (int nt = 0; nt < 8; nt++) {
                sc[mt][nt][0] = fexp(sc[mt][nt][0] - mx0[mt]); a0 += sc[mt][nt][0];
                sc[mt][nt][1] = fexp(sc[mt][nt][1] - mx0[mt]); a0 += sc[mt][nt][1];
                sc[mt][nt][2] = fexp(sc[mt][nt][2] - mx1[mt]); a1 += sc[mt][nt][2];
                sc[mt][nt][3] = fexp(sc[mt][nt][3] - mx1[mt]); a1 += sc[mt][nt][3];
            }
            a0 += __shfl_xor_sync(0xffffffffu, a0, 1);
            a0 += __shfl_xor_sync(0xffffffffu, a0, 2);
            a1 += __shfl_xor_sync(0xffffffffu, a1, 1);
            a1 += __shfl_xor_sync(0xffffffffu, a1, 2);
            s0[mt] = a0; s1[mt] = a1;
        }

        if (h2 == 0) {       // v needed from here on; wait once
            CP_WAIT0();
            __syncthreads();
        }

        float pv[2][4][4];
#pragma unroll
        for (int mt = 0; mt < 2; mt++)
#pragma unroll
            for (int nt = 0; nt < 4; nt++)
#pragma unroll
                for (int i = 0; i < 4; i++) pv[mt][nt][i] = 0.f;

#pragma unroll
        for (int ks2 = 0; ks2 < 4; ks2++) {
            unsigned vb[4][2];
            uint32_t va = vB + ks2 * 24576;
            ldsm4t(vb[0][0], vb[0][1], vb[1][0], vb[1][1], va);
            ldsm4t(vb[2][0], vb[2][1], vb[3][0], vb[3][1], va ^ 32);
#pragma unroll
            for (int mt = 0; mt < 2; mt++) {
                unsigned pf[4];
                pf[0] = pack2(sc[mt][2 * ks2][0],     sc[mt][2 * ks2][1]);
                pf[1] = pack2(sc[mt][2 * ks2][2],     sc[mt][2 * ks2][3]);
                pf[2] = pack2(sc[mt][2 * ks2 + 1][0], sc[mt][2 * ks2 + 1][1]);
                pf[3] = pack2(sc[mt][2 * ks2 + 1][2], sc[mt][2 * ks2 + 1][3]);
#pragma unroll
                for (int nt = 0; nt < 4; nt++)
                    mma_f16(pv[mt][nt], pf, vb[nt]);
            }
        }

#pragma unroll
        for (int mt = 0; mt < 2; mt++) {
            float i0 = 1.f / s0[mt], i1 = 1.f / s1[mt];
            int row = (mt0 + mt) * 16 + gid;
            __half* o0 = aout + ((size_t)b * 64 + row) * 256 + h * 32 + 2 * tig;
            __half* o1 = o0 + 8 * 256;
#pragma unroll
            for (int nt = 0; nt < 4; nt++) {
                *(__half2*)(o0 + nt * 8) =
                    __floats2half2_rn(pv[mt][nt][0] * i0, pv[mt][nt][1] * i0);
                *(__half2*)(o1 + nt * 8) =
                    __floats2half2_rn(pv[mt][nt][2] * i1, pv[mt][nt][3] * i1);
            }
        }
    }
}

// ---------------------------------------------------------------------------
extern "C" void kernel_launch(void* const* d_in, const int* in_sizes, int n_in,
                              void* d_out, int out_size)
{
    const float* x   = (const float*)d_in[0];
    const float* qw  = (const float*)d_in[1];
    const float* qb  = (const float*)d_in[2];
    const float* pw  = (const float*)d_in[3];
    const float* pb  = (const float*)d_in[4];
    const float* tab = (const float*)d_in[5];
    const int*   rpi = (const int*)d_in[6];
    float* out = (float*)d_out;

    __half *xh = nullptr, *qkvh = nullptr, *aouth = nullptr, *wh = nullptr, *bh = nullptr;
    cudaGetSymbolAddress((void**)&xh,    g_xh);
    cudaGetSymbolAddress((void**)&qkvh,  g_qkvh);
    cudaGetSymbolAddress((void**)&aouth, g_aouth);
    cudaGetSymbolAddress((void**)&wh,    g_wh);
    cudaGetSymbolAddress((void**)&bh,    g_biash);

    const int smemBytes = GNSTAGE * GSTAGE_B;  // 98304 B
    cudaFuncSetAttribute(gemm_cp_kernel<__half>,
                         cudaFuncAttributeMaxDynamicSharedMemorySize, smemBytes);
    cudaFuncSetAttribute(gemm_cp_kernel<float>,
                         cudaFuncAttributeMaxDynamicSharedMemorySize, smemBytes);
    const int attnSmem = 98304;              // 96 KB
    cudaFuncSetAttribute(attn_mma_kernel,
                         cudaFuncAttributeMaxDynamicSharedMemorySize, attnSmem);

    // fp32 -> fp16 conversions + bias table
    f2h_kernel<<<32768, 256>>>(x, xh, 134217728 / 4);
    f2h_kernel<<<192, 256>>>(qw, wh, 196608 / 4);
    f2h_kernel<<<64, 256>>>(pw, wh + 196608, 65536 / 4);
    bias_pre_kernel<<<16, 256>>>(tab, rpi, bh);

    // QKV projection: [524288,256] @ [768,256]^T + b  -> fp16 qkv
    dim3 g1(768 / 128, (8192 * 64) / 128);   // (6, 4096)
    gemm_cp_kernel<__half><<<g1, 256, smemBytes>>>(xh, wh, qb, qkvh, 768);

    // Tensor-core windowed attention (fp16 io)
    attn_mma_kernel<<<8192, 256, attnSmem>>>(qkvh, bh, aouth);

    // Output projection: [524288,256] @ [256,256]^T + b -> fp32 out
    dim3 g3(256 / 128, (8192 * 64) / 128);   // (2, 4096)
    gemm_cp_kernel<float><<<g3, 256, smemBytes>>>(aouth, wh + 196608, pb, out, 256);
}

// round 15
// speedup vs baseline: 1.0297x; 1.0297x over previous
#include <cuda_runtime.h>
#include <cuda_fp16.h>
#include <cstdint>

// ---------------------------------------------------------------------------
// LeWinAttention round 15: A-resident GEMM (A smem-resident across all
// n-tiles, B streamed via 4-stage cp.async ring) + x-convert fused into the
// qkv GEMM's A-load. f2h(x) pass and g_xh deleted. Attention = R13 version.
// ---------------------------------------------------------------------------

__device__ __half g_qkvh[402653184];  // qkv fp16        (768 MB)
__device__ __half g_aouth[134217728]; // attn out fp16   (256 MB)
__device__ __half g_wh[262144];       // qkv_w + proj_w
__device__ __half g_biash[32768];     // bias [8][64][64] fp16

// ---------------- helpers --------------------------------------------------
__device__ __forceinline__ void mma_f16(float* d, const unsigned* a, const unsigned* b) {
    asm volatile(
        "mma.sync.aligned.m16n8k16.row.col.f32.f16.f16.f32 "
        "{%0,%1,%2,%3}, {%4,%5,%6,%7}, {%8,%9}, {%0,%1,%2,%3};"
        : "+f"(d[0]), "+f"(d[1]), "+f"(d[2]), "+f"(d[3])
        : "r"(a[0]), "r"(a[1]), "r"(a[2]), "r"(a[3]), "r"(b[0]), "r"(b[1]));
}
__device__ __forceinline__ void ldsm4(unsigned& r0, unsigned& r1, unsigned& r2,
                                      unsigned& r3, uint32_t addr) {
    asm volatile("ldmatrix.sync.aligned.m8n8.x4.shared.b16 {%0,%1,%2,%3}, [%4];"
                 : "=r"(r0), "=r"(r1), "=r"(r2), "=r"(r3) : "r"(addr));
}
__device__ __forceinline__ void ldsm4t(unsigned& r0, unsigned& r1, unsigned& r2,
                                       unsigned& r3, uint32_t addr) {
    asm volatile("ldmatrix.sync.aligned.m8n8.x4.trans.shared.b16 {%0,%1,%2,%3}, [%4];"
                 : "=r"(r0), "=r"(r1), "=r"(r2), "=r"(r3) : "r"(addr));
}
__device__ __forceinline__ void cpasync16(uint32_t dst, const void* src) {
    asm volatile("cp.async.cg.shared.global [%0], [%1], 16;" :: "r"(dst), "l"(src));
}
#define CP_COMMIT() asm volatile("cp.async.commit_group;" ::: "memory")
#define CP_WAIT2()  asm volatile("cp.async.wait_group 2;" ::: "memory")
#define CP_WAIT0()  asm volatile("cp.async.wait_group 0;" ::: "memory")

__device__ __forceinline__ void store2(float* p, float v0, float v1) {
    *(float2*)p = make_float2(v0, v1);
}
__device__ __forceinline__ void store2(__half* p, float v0, float v1) {
    *(__half2*)p = __floats2half2_rn(v0, v1);
}
__device__ __forceinline__ unsigned pack2(float x, float y) {
    __half2 h = __floats2half2_rn(x, y);
    return *(unsigned*)&h;
}

// FMA-pipe exp (no MUFU): exp(x) for x <= 0. rel err ~2e-6.
__device__ __forceinline__ float fexp(float x) {
    float y = fmaxf(x * 1.4426950408889634f, -126.0f);
    float r = y + 12582912.0f;
    float k = r - 12582912.0f;
    float f = y - k;
    float p = 0.0013333558f;
    p = fmaf(p, f, 0.0096181291f);
    p = fmaf(p, f, 0.0555041087f);
    p = fmaf(p, f, 0.2402264676f);
    p = fmaf(p, f, 0.6931471806f);
    p = fmaf(p, f, 1.0f);
    return __int_as_float(__float_as_int(p) + (((int)k) << 23));
}

// ---------------------------------------------------------------------------
__global__ void f2h_kernel(const float* __restrict__ in, __half* __restrict__ out, int n4)
{
    for (int i = blockIdx.x * blockDim.x + threadIdx.x; i < n4;
         i += gridDim.x * blockDim.x) {
        float4 v = *(const float4*)(in + (size_t)i * 4);
        __half2 h0 = __floats2half2_rn(v.x, v.y);
        __half2 h1 = __floats2half2_rn(v.z, v.w);
        uint2 u;
        u.x = *(unsigned*)&h0; u.y = *(unsigned*)&h1;
        *(uint2*)(out + (size_t)i * 4) = u;
    }
}

__global__ void bias_pre_kernel(const float* __restrict__ table,
                                const int* __restrict__ rpi,
                                __half* __restrict__ biash)
{
    int i = blockIdx.x * 256 + threadIdx.x;
    if (i < 4096) {
        int idx = rpi[i];
#pragma unroll
        for (int h = 0; h < 8; h++)
            biash[h * 4096 + i] = __float2half(table[idx * 8 + h]);
    }
}

// ---------------------------------------------------------------------------
// A-resident GEMM: C[M,Nc] = A[M,256] @ W[Nc,256]^T + bias.
// One CTA per 128-row m-block; A[128][256]h stays in smem (8 k-blocks x 8KB,
// 16B-chunk swizzle chunk' = chunk ^ ((row>>1)&3)); loops NT n-tiles of 128,
// streaming B k-blocks (8KB each) through a 4-stage cp.async ring.
// InT = float (qkv: fused fp32->fp16 convert) or __half (proj).
// smem: A 64KB @0, B ring 32KB @65536. 2 CTAs/SM.
// ---------------------------------------------------------------------------
#define RB_OFF  65536
#define RSTAGE  8192

template <typename InT, typename OutT>
__global__ void __launch_bounds__(256, 2)
gemm_res_kernel(const InT* __restrict__ A, const __half* __restrict__ W,
                const float* __restrict__ bias, OutT* __restrict__ C,
                int Nc, int NT)
{
    extern __shared__ char sm[];
    uint32_t sbase;
    asm("{ .reg .u64 t; cvta.to.shared.u64 t, %1; cvt.u32.u64 %0, t; }"
        : "=r"(sbase) : "l"(sm));

    const int t    = threadIdx.x;
    const int lane = t & 31;
    const int gid  = lane >> 2;
    const int tig  = lane & 3;
    const int w    = t >> 5;
    const int wm   = w & 3;              // 4 warps in m
    const int wn   = w >> 2;             // 2 warps in n
    const size_t mBase = (size_t)blockIdx.x * 128;

    // ---- Phase 1: load A[128,256] into smem (once per CTA)
    if (sizeof(InT) == 4) {
        // fp32 source: LDG float4 x2 -> cvt -> STS.128 (16 chunks/thread)
        const float* Af = (const float*)A;
#pragma unroll
        for (int i = 0; i < 16; i++) {
            int g16 = t + (i << 8);
            int row = g16 >> 5;
            int c   = g16 & 31;                // 16B chunk within row
            const float* src = Af + (mBase + row) * 256 + c * 8;
            float4 v0 = *(const float4*)(src);
            float4 v1 = *(const float4*)(src + 4);
            uint32_t off = (uint32_t)((c >> 2) * RSTAGE + row * 64
                          + (((c & 3) ^ ((row >> 1) & 3)) << 4));
            uint4 u = make_uint4(pack2(v0.x, v0.y), pack2(v0.z, v0.w),
                                 pack2(v1.x, v1.y), pack2(v1.z, v1.w));
            *(uint4*)(sm + off) = u;
        }
    } else {
        // fp16 source: cp.async (group 0)
        const __half* Ah = (const __half*)A;
#pragma unroll
        for (int i = 0; i < 16; i++) {
            int g16 = t + (i << 8);
            int row = g16 >> 5;
            int c   = g16 & 31;
            uint32_t off = (uint32_t)((c >> 2) * RSTAGE + row * 64
                          + (((c & 3) ^ ((row >> 1) & 3)) << 4));
            cpasync16(sbase + off, Ah + (mBase + row) * 256 + c * 8);
        }
        CP_COMMIT();
    }

    // ---- B streaming setup: 2 chunks per thread per 8KB k-block
    const int r0c = t >> 2;              // rows r0c and 64+r0c
    const int cc  = t & 3;
    const int csw0 = (cc ^ ((r0c >> 1) & 3)) << 4;
    const int csw1 = (cc ^ (((64 + r0c) >> 1) & 3)) << 4;  // == csw0 (row+64)
    const uint32_t dB0 = sbase + RB_OFF + r0c * 64 + csw0;
    const uint32_t dB1 = sbase + RB_OFF + (64 + r0c) * 64 + csw1;

    auto issueB = [&](int g) {           // g = global k-block id (nt*8 + kb)
        const int nt = g >> 3, kb = g & 7;
        const __half* s0 = W + (size_t)(nt * 128 + r0c) * 256 + kb * 32 + cc * 8;
        const uint32_t so = (uint32_t)(g & 3) * RSTAGE;
        cpasync16(dB0 + so, s0);
        cpasync16(dB1 + so, s0 + (size_t)64 * 256);
    };

    // ---- ldmatrix addresses
    uint32_t aAddr[2], bAddr[4];
#pragma unroll
    for (int mt = 0; mt < 2; mt++) {
        int row = wm * 32 + mt * 16 + ((lane >> 3) & 1) * 8 + (lane & 7);
        aAddr[mt] = sbase + row * 64 + ((((lane >> 4) ^ ((row >> 1) & 3))) << 4);
    }
#pragma unroll
    for (int q = 0; q < 4; q++) {
        int n = wn * 64 + q * 16 + ((lane >> 4) << 3) + (lane & 7);
        bAddr[q] = sbase + RB_OFF + n * 64
                 + ((((lane >> 3) & 1) ^ ((n >> 1) & 3)) << 4);
    }

    float acc[2][8][4];
#pragma unroll
    for (int mt = 0; mt < 2; mt++)
#pragma unroll
        for (int jt = 0; jt < 8; jt++)
#pragma unroll
            for (int i = 0; i < 4; i++) acc[mt][jt][i] = 0.f;

    // prologue: 3 B blocks in flight
    issueB(0); CP_COMMIT();
    issueB(1); CP_COMMIT();
    issueB(2); CP_COMMIT();

    const int GTOT = NT * 8;
    for (int g = 0; g < GTOT; g++) {
        CP_WAIT2();          // B block g landed (and A group, first iters)
        __syncthreads();

        const uint32_t soB = (uint32_t)(g & 3) * RSTAGE;
        const uint32_t soA = (uint32_t)(g & 7) * RSTAGE;
#pragma unroll
        for (int kk = 0; kk < 2; kk++) {
            const uint32_t kx = kk << 5;
            unsigned af[2][4], bf[8][2];
#pragma unroll
            for (int mt = 0; mt < 2; mt++)
                ldsm4(af[mt][0], af[mt][1], af[mt][2], af[mt][3],
                      (aAddr[mt] + soA) ^ kx);
#pragma unroll
            for (int q = 0; q < 4; q++)
                ldsm4(bf[2 * q][0], bf[2 * q][1], bf[2 * q + 1][0], bf[2 * q + 1][1],
                      (bAddr[q] + soB) ^ kx);
#pragma unroll
            for (int mt = 0; mt < 2; mt++)
#pragma unroll
                for (int jt = 0; jt < 8; jt++)
                    mma_f16(acc[mt][jt], af[mt], bf[jt]);
        }

        if (g + 3 < GTOT) issueB(g + 3);
        CP_COMMIT();         // one group per iter keeps wait counting exact

        if ((g & 7) == 7) {
            // ---- epilogue for n-tile nt = g>>3
            const int nBase = (g >> 3) * 128;
#pragma unroll
            for (int mt = 0; mt < 2; mt++) {
#pragma unroll
                for (int jt = 0; jt < 8; jt++) {
                    int col = nBase + wn * 64 + jt * 8 + (tig << 1);
                    float b0 = bias[col], b1 = bias[col + 1];
                    size_t r0 = mBase + wm * 32 + mt * 16 + gid;
                    store2(C + r0 * Nc + col, acc[mt][jt][0] + b0, acc[mt][jt][1] + b1);
                    store2(C + (r0 + 8) * Nc + col, acc[mt][jt][2] + b0, acc[mt][jt][3] + b1);
#pragma unroll
                    for (int i = 0; i < 4; i++) acc[mt][jt][i] = 0.f;
                }
            }
        }
    }
}

// ---------------------------------------------------------------------------
// Tensor-core attention (R13 version): 1 CTA per window, warp = head.
// ---------------------------------------------------------------------------
__global__ void __launch_bounds__(256)
attn_mma_kernel(const __half* __restrict__ qkv, const __half* __restrict__ biash,
                __half* __restrict__ aout)
{
    extern __shared__ char sm[];
    uint32_t sbase;
    asm("{ .reg .u64 t; cvta.to.shared.u64 t, %1; cvt.u32.u64 %0, t; }"
        : "=r"(sbase) : "l"(sm));

    const int b    = blockIdx.x;
    const int t    = threadIdx.x;
    const int lane = t & 31;
    const int h    = t >> 5;
    const int gid  = lane >> 2;
    const int tig  = lane & 3;

    {
        const int r = t >> 2;
        const __half* src = qkv + ((size_t)b * 64 + r) * 768 + (t & 3) * 8;
        const uint32_t drow = sbase + r * 1536;
        const int rx = r & 7;
#pragma unroll
        for (int i = 0; i < 24; i++) {
            int cc = (t & 3) + (i << 2);
            cpasync16(drow + ((cc ^ rx) << 4), src + (i << 5));
        }
    }
    CP_COMMIT();
    CP_WAIT0();
    __syncthreads();

    uint32_t qA, kB, vB;
    {
        int r = ((lane >> 3) & 1) * 8 + (lane & 7);
        int ck = (h << 2) | (lane >> 4);
        qA = sbase + r * 1536 + ((ck ^ (r & 7)) << 4);
    }
    {
        int r = ((lane >> 4) << 3) + (lane & 7);
        int ck = ((8 + h) << 2) | ((lane >> 3) & 1);
        kB = sbase + r * 1536 + ((ck ^ (r & 7)) << 4);
    }
    {
        int tt = lane >> 3;
        int r = (tt & 1) * 8 + (lane & 7);
        int ck = ((16 + h) << 2) | (tt >> 1);
        vB = sbase + r * 1536 + ((ck ^ (r & 7)) << 4);
    }

    const float scale = 0.17677669529663687f;
    const __half* bia = biash + h * 4096;

#pragma unroll
    for (int h2 = 0; h2 < 2; h2++) {
        const int mt0 = h2 * 2;

        float sc[2][8][4];
#pragma unroll
        for (int mt = 0; mt < 2; mt++)
#pragma unroll
            for (int nt = 0; nt < 8; nt++)
#pragma unroll
                for (int i = 0; i < 4; i++) sc[mt][nt][i] = 0.f;

        unsigned kf[8][2][2];
#pragma unroll
        for (int ks = 0; ks < 2; ks++)
#pragma unroll
            for (int q = 0; q < 4; q++)
                ldsm4(kf[2 * q][ks][0], kf[2 * q][ks][1],
                      kf[2 * q + 1][ks][0], kf[2 * q + 1][ks][1],
                      (kB + q * 24576) ^ (ks << 5));
#pragma unroll
        for (int mt = 0; mt < 2; mt++)
#pragma unroll
            for (int ks = 0; ks < 2; ks++) {
                unsigned af[4];
                ldsm4(af[0], af[1], af[2], af[3],
                      (qA + (mt0 + mt) * 24576) ^ (ks << 5));
#pragma unroll
                for (int nt = 0; nt < 8; nt++)
                    mma_f16(sc[mt][nt], af, kf[nt][ks]);
            }

        float mx0[2], mx1[2];
#pragma unroll
        for (int mt = 0; mt < 2; mt++) {
            float m0 = -1e30f, m1 = -1e30f;
            int row = (mt0 + mt) * 16 + gid;
#pragma unroll
            for (int nt = 0; nt < 8; nt++) {
                float2 b0 = __half22float2(*(const __half2*)(bia + row * 64 + nt * 8 + 2 * tig));
                float2 b1 = __half22float2(*(const __half2*)(bia + (row + 8) * 64 + nt * 8 + 2 * tig));
                sc[mt][nt][0] = fmaf(sc[mt][nt][0], scale, b0.x);
                sc[mt][nt][1] = fmaf(sc[mt][nt][1], scale, b0.y);
                sc[mt][nt][2] = fmaf(sc[mt][nt][2], scale, b1.x);
                sc[mt][nt][3] = fmaf(sc[mt][nt][3], scale, b1.y);
                m0 = fmaxf(m0, fmaxf(sc[mt][nt][0], sc[mt][nt][1]));
                m1 = fmaxf(m1, fmaxf(sc[mt][nt][2], sc[mt][nt][3]));
            }
            m0 = fmaxf(m0, __shfl_xor_sync(0xffffffffu, m0, 1));
            m0 = fmaxf(m0, __shfl_xor_sync(0xffffffffu, m0, 2));
            m1 = fmaxf(m1, __shfl_xor_sync(0xffffffffu, m1, 1));
            m1 = fmaxf(m1, __shfl_xor_sync(0xffffffffu, m1, 2));
            mx0[mt] = m0; mx1[mt] = m1;
        }

        float s0[2], s1[2];
#pragma unroll
        for (int mt = 0; mt < 2; mt++) {
            float a0 = 0.f, a1 = 0.f;
#pragma unroll
            for (int nt = 0; nt < 8; nt++) {
                sc[mt][nt][0] = fexp(sc[mt][nt][0] - mx0[mt]); a0 += sc[mt][nt][0];
                sc[mt][nt][1] = fexp(sc[mt][nt][1] - mx0[mt]); a0 += sc[mt][nt][1];
                sc[mt][nt][2] = fexp(sc[mt][nt][2] - mx1[mt]); a1 += sc[mt][nt][2];
                sc[mt][nt][3] = fexp(sc[mt][nt][3] - mx1[mt]); a1 += sc[mt][nt][3];
            }
            a0 += __shfl_xor_sync(0xffffffffu, a0, 1);
            a0 += __shfl_xor_sync(0xffffffffu, a0, 2);
            a1 += __shfl_xor_sync(0xffffffffu, a1, 1);
            a1 += __shfl_xor_sync(0xffffffffu, a1, 2);
            s0[mt] = a0; s1[mt] = a1;
        }

        float pv[2][4][4];
#pragma unroll
        for (int mt = 0; mt < 2; mt++)
#pragma unroll
            for (int nt = 0; nt < 4; nt++)
#pragma unroll
                for (int i = 0; i < 4; i++) pv[mt][nt][i] = 0.f;

#pragma unroll
        for (int ks2 = 0; ks2 < 4; ks2++) {
            unsigned vb[4][2];
            uint32_t va = vB + ks2 * 24576;
            ldsm4t(vb[0][0], vb[0][1], vb[1][0], vb[1][1], va);
            ldsm4t(vb[2][0], vb[2][1], vb[3][0], vb[3][1], va ^ 32);
#pragma unroll
            for (int mt = 0; mt < 2; mt++) {
                unsigned pf[4];
                pf[0] = pack2(sc[mt][2 * ks2][0],     sc[mt][2 * ks2][1]);
                pf[1] = pack2(sc[mt][2 * ks2][2],     sc[mt][2 * ks2][3]);
                pf[2] = pack2(sc[mt][2 * ks2 + 1][0], sc[mt][2 * ks2 + 1][1]);
                pf[3] = pack2(sc[mt][2 * ks2 + 1][2], sc[mt][2 * ks2 + 1][3]);
#pragma unroll
                for (int nt = 0; nt < 4; nt++)
                    mma_f16(pv[mt][nt], pf, vb[nt]);
            }
        }

#pragma unroll
        for (int mt = 0; mt < 2; mt++) {
            float i0 = 1.f / s0[mt], i1 = 1.f / s1[mt];
            int row = (mt0 + mt) * 16 + gid;
            __half* o0 = aout + ((size_t)b * 64 + row) * 256 + h * 32 + 2 * tig;
            __half* o1 = o0 + 8 * 256;
#pragma unroll
            for (int nt = 0; nt < 4; nt++) {
                *(__half2*)(o0 + nt * 8) =
                    __floats2half2_rn(pv[mt][nt][0] * i0, pv[mt][nt][1] * i0);
                *(__half2*)(o1 + nt * 8) =
                    __floats2half2_rn(pv[mt][nt][2] * i1, pv[mt][nt][3] * i1);
            }
        }
    }
}

// ---------------------------------------------------------------------------
extern "C" void kernel_launch(void* const* d_in, const int* in_sizes, int n_in,
                              void* d_out, int out_size)
{
    const float* x   = (const float*)d_in[0];
    const float* qw  = (const float*)d_in[1];
    const float* qb  = (const float*)d_in[2];
    const float* pw  = (const float*)d_in[3];
    const float* pb  = (const float*)d_in[4];
    const float* tab = (const float*)d_in[5];
    const int*   rpi = (const int*)d_in[6];
    float* out = (float*)d_out;

    __half *qkvh = nullptr, *aouth = nullptr, *wh = nullptr, *bh = nullptr;
    cudaGetSymbolAddress((void**)&qkvh,  g_qkvh);
    cudaGetSymbolAddress((void**)&aouth, g_aouth);
    cudaGetSymbolAddress((void**)&wh,    g_wh);
    cudaGetSymbolAddress((void**)&bh,    g_biash);

    const int gemmSmem = RB_OFF + 4 * RSTAGE;   // 98304 B
    cudaFuncSetAttribute((const void*)gemm_res_kernel<float, __half>,
                         cudaFuncAttributeMaxDynamicSharedMemorySize, gemmSmem);
    cudaFuncSetAttribute((const void*)gemm_res_kernel<__half, float>,
                         cudaFuncAttributeMaxDynamicSharedMemorySize, gemmSmem);
    const int attnSmem = 98304;
    cudaFuncSetAttribute((const void*)attn_mma_kernel,
                         cudaFuncAttributeMaxDynamicSharedMemorySize, attnSmem);

    // weight converts + bias table (tiny)
    f2h_kernel<<<192, 256>>>(qw, wh, 196608 / 4);
    f2h_kernel<<<64, 256>>>(pw, wh + 196608, 65536 / 4);
    bias_pre_kernel<<<16, 256>>>(tab, rpi, bh);

    // QKV projection (fused x fp32->fp16): [524288,256] @ [768,256]^T + b
    gemm_res_kernel<float, __half><<<4096, 256, gemmSmem>>>(x, wh, qb, qkvh, 768, 6);

    // Tensor-core windowed attention (fp16 io)
    attn_mma_kernel<<<8192, 256, attnSmem>>>(qkvh, bh, aouth);

    // Output projection: [524288,256] @ [256,256]^T + b -> fp32 out
    gemm_res_kernel<__half, float><<<4096, 256, gemmSmem>>>(aouth, wh + 196608, pb, out, 256, 2);
}

// round 16
// speedup vs baseline: 1.0664x; 1.0356x over previous
#include <cuda_runtime.h>
#include <cuda_fp16.h>
#include <cstdint>

// ---------------------------------------------------------------------------
// LeWinAttention round 16: R15 with GEMM warp tile 64x64 (128 thr / 4 warps,
// 2m x 2n) to cut smem-crossbar bytes per MAC by 33%. A-resident + fused
// x-convert unchanged; attention unchanged.
// ---------------------------------------------------------------------------

__device__ __half g_qkvh[402653184];  // qkv fp16        (768 MB)
__device__ __half g_aouth[134217728]; // attn out fp16   (256 MB)
__device__ __half g_wh[262144];       // qkv_w + proj_w
__device__ __half g_biash[32768];     // bias [8][64][64] fp16

// ---------------- helpers --------------------------------------------------
__device__ __forceinline__ void mma_f16(float* d, const unsigned* a, const unsigned* b) {
    asm volatile(
        "mma.sync.aligned.m16n8k16.row.col.f32.f16.f16.f32 "
        "{%0,%1,%2,%3}, {%4,%5,%6,%7}, {%8,%9}, {%0,%1,%2,%3};"
        : "+f"(d[0]), "+f"(d[1]), "+f"(d[2]), "+f"(d[3])
        : "r"(a[0]), "r"(a[1]), "r"(a[2]), "r"(a[3]), "r"(b[0]), "r"(b[1]));
}
__device__ __forceinline__ void ldsm4(unsigned& r0, unsigned& r1, unsigned& r2,
                                      unsigned& r3, uint32_t addr) {
    asm volatile("ldmatrix.sync.aligned.m8n8.x4.shared.b16 {%0,%1,%2,%3}, [%4];"
                 : "=r"(r0), "=r"(r1), "=r"(r2), "=r"(r3) : "r"(addr));
}
__device__ __forceinline__ void ldsm4t(unsigned& r0, unsigned& r1, unsigned& r2,
                                       unsigned& r3, uint32_t addr) {
    asm volatile("ldmatrix.sync.aligned.m8n8.x4.trans.shared.b16 {%0,%1,%2,%3}, [%4];"
                 : "=r"(r0), "=r"(r1), "=r"(r2), "=r"(r3) : "r"(addr));
}
__device__ __forceinline__ void cpasync16(uint32_t dst, const void* src) {
    asm volatile("cp.async.cg.shared.global [%0], [%1], 16;" :: "r"(dst), "l"(src));
}
#define CP_COMMIT() asm volatile("cp.async.commit_group;" ::: "memory")
#define CP_WAIT2()  asm volatile("cp.async.wait_group 2;" ::: "memory")
#define CP_WAIT0()  asm volatile("cp.async.wait_group 0;" ::: "memory")

__device__ __forceinline__ void store2(float* p, float v0, float v1) {
    *(float2*)p = make_float2(v0, v1);
}
__device__ __forceinline__ void store2(__half* p, float v0, float v1) {
    *(__half2*)p = __floats2half2_rn(v0, v1);
}
__device__ __forceinline__ unsigned pack2(float x, float y) {
    __half2 h = __floats2half2_rn(x, y);
    return *(unsigned*)&h;
}

// FMA-pipe exp (no MUFU): exp(x) for x <= 0. rel err ~2e-6.
__device__ __forceinline__ float fexp(float x) {
    float y = fmaxf(x * 1.4426950408889634f, -126.0f);
    float r = y + 12582912.0f;
    float k = r - 12582912.0f;
    float f = y - k;
    float p = 0.0013333558f;
    p = fmaf(p, f, 0.0096181291f);
    p = fmaf(p, f, 0.0555041087f);
    p = fmaf(p, f, 0.2402264676f);
    p = fmaf(p, f, 0.6931471806f);
    p = fmaf(p, f, 1.0f);
    return __int_as_float(__float_as_int(p) + (((int)k) << 23));
}

// ---------------------------------------------------------------------------
__global__ void f2h_kernel(const float* __restrict__ in, __half* __restrict__ out, int n4)
{
    for (int i = blockIdx.x * blockDim.x + threadIdx.x; i < n4;
         i += gridDim.x * blockDim.x) {
        float4 v = *(const float4*)(in + (size_t)i * 4);
        __half2 h0 = __floats2half2_rn(v.x, v.y);
        __half2 h1 = __floats2half2_rn(v.z, v.w);
        uint2 u;
        u.x = *(unsigned*)&h0; u.y = *(unsigned*)&h1;
        *(uint2*)(out + (size_t)i * 4) = u;
    }
}

__global__ void bias_pre_kernel(const float* __restrict__ table,
                                const int* __restrict__ rpi,
                                __half* __restrict__ biash)
{
    int i = blockIdx.x * 256 + threadIdx.x;
    if (i < 4096) {
        int idx = rpi[i];
#pragma unroll
        for (int h = 0; h < 8; h++)
            biash[h * 4096 + i] = __float2half(table[idx * 8 + h]);
    }
}

// ---------------------------------------------------------------------------
// A-resident GEMM: C[M,Nc] = A[M,256] @ W[Nc,256]^T + bias.
// 128 threads / 4 warps (2m x 2n), warp tile 64x64, CTA tile 128x128.
// A[128][256]h smem-resident (8 k-blocks x 8KB); B streamed via 4-stage ring.
// smem: A 64KB @0, B ring 32KB @65536 -> 96KB, 2 CTAs/SM.
// ---------------------------------------------------------------------------
#define RB_OFF  65536
#define RSTAGE  8192

template <typename InT, typename OutT>
__global__ void __launch_bounds__(128, 2)
gemm_res_kernel(const InT* __restrict__ A, const __half* __restrict__ W,
                const float* __restrict__ bias, OutT* __restrict__ C,
                int Nc, int NT)
{
    extern __shared__ char sm[];
    uint32_t sbase;
    asm("{ .reg .u64 t; cvta.to.shared.u64 t, %1; cvt.u32.u64 %0, t; }"
        : "=r"(sbase) : "l"(sm));

    const int t    = threadIdx.x;
    const int lane = t & 31;
    const int gid  = lane >> 2;
    const int tig  = lane & 3;
    const int w    = t >> 5;
    const int wm   = w & 1;              // 2 warps in m (64 rows each)
    const int wn   = w >> 1;             // 2 warps in n (64 cols each)
    const size_t mBase = (size_t)blockIdx.x * 128;

    // ---- Phase 1: load A[128,256] into smem (once per CTA); 32 chunks/thread
    if (sizeof(InT) == 4) {
        const float* Af = (const float*)A;
#pragma unroll
        for (int i = 0; i < 32; i++) {
            int g16 = t + (i << 7);
            int row = g16 >> 5;
            int c   = g16 & 31;
            const float* src = Af + (mBase + row) * 256 + c * 8;
            float4 v0 = *(const float4*)(src);
            float4 v1 = *(const float4*)(src + 4);
            uint32_t off = (uint32_t)((c >> 2) * RSTAGE + row * 64
                          + (((c & 3) ^ ((row >> 1) & 3)) << 4));
            uint4 u = make_uint4(pack2(v0.x, v0.y), pack2(v0.z, v0.w),
                                 pack2(v1.x, v1.y), pack2(v1.z, v1.w));
            *(uint4*)(sm + off) = u;
        }
    } else {
        const __half* Ah = (const __half*)A;
#pragma unroll
        for (int i = 0; i < 32; i++) {
            int g16 = t + (i << 7);
            int row = g16 >> 5;
            int c   = g16 & 31;
            uint32_t off = (uint32_t)((c >> 2) * RSTAGE + row * 64
                          + (((c & 3) ^ ((row >> 1) & 3)) << 4));
            cpasync16(sbase + off, Ah + (mBase + row) * 256 + c * 8);
        }
        CP_COMMIT();
    }

    // ---- B streaming: 4 chunks/thread per 8KB k-block (rows r0c+32j)
    const int r0c = t >> 2;              // 0..31
    const int cc  = t & 3;
    const int csw = (cc ^ ((r0c >> 1) & 3)) << 4;  // same for r0c+32j
    uint32_t dB[4];
#pragma unroll
    for (int j = 0; j < 4; j++)
        dB[j] = sbase + RB_OFF + (r0c + 32 * j) * 64 + csw;

    auto issueB = [&](int g) {           // g = nt*8 + kb
        const int nt = g >> 3, kb = g & 7;
        const __half* s0 = W + (size_t)(nt * 128 + r0c) * 256 + kb * 32 + cc * 8;
        const uint32_t so = (uint32_t)(g & 3) * RSTAGE;
#pragma unroll
        for (int j = 0; j < 4; j++)
            cpasync16(dB[j] + so, s0 + (size_t)(32 * j) * 256);
    };

    // ---- ldmatrix addresses
    uint32_t aAddr[4], bAddr[4];
#pragma unroll
    for (int mt = 0; mt < 4; mt++) {
        int row = wm * 64 + mt * 16 + ((lane >> 3) & 1) * 8 + (lane & 7);
        aAddr[mt] = sbase + row * 64 + ((((lane >> 4) ^ ((row >> 1) & 3))) << 4);
    }
#pragma unroll
    for (int q = 0; q < 4; q++) {
        int n = wn * 64 + q * 16 + ((lane >> 4) << 3) + (lane & 7);
        bAddr[q] = sbase + RB_OFF + n * 64
                 + ((((lane >> 3) & 1) ^ ((n >> 1) & 3)) << 4);
    }

    float acc[4][8][4];
#pragma unroll
    for (int mt = 0; mt < 4; mt++)
#pragma unroll
        for (int jt = 0; jt < 8; jt++)
#pragma unroll
            for (int i = 0; i < 4; i++) acc[mt][jt][i] = 0.f;

    // prologue: 3 B blocks in flight
    issueB(0); CP_COMMIT();
    issueB(1); CP_COMMIT();
    issueB(2); CP_COMMIT();

    const int GTOT = NT * 8;
    for (int g = 0; g < GTOT; g++) {
        CP_WAIT2();          // B block g landed (and A group, first iters)
        __syncthreads();

        const uint32_t soB = (uint32_t)(g & 3) * RSTAGE;
        const uint32_t soA = (uint32_t)(g & 7) * RSTAGE;
#pragma unroll
        for (int kk = 0; kk < 2; kk++) {
            const uint32_t kx = kk << 5;
            unsigned af[4][4], bf[8][2];
#pragma unroll
            for (int mt = 0; mt < 4; mt++)
                ldsm4(af[mt][0], af[mt][1], af[mt][2], af[mt][3],
                      (aAddr[mt] + soA) ^ kx);
#pragma unroll
            for (int q = 0; q < 4; q++)
                ldsm4(bf[2 * q][0], bf[2 * q][1], bf[2 * q + 1][0], bf[2 * q + 1][1],
                      (bAddr[q] + soB) ^ kx);
#pragma unroll
            for (int mt = 0; mt < 4; mt++)
#pragma unroll
                for (int jt = 0; jt < 8; jt++)
                    mma_f16(acc[mt][jt], af[mt], bf[jt]);
        }

        if (g + 3 < GTOT) issueB(g + 3);
        CP_COMMIT();         // one group per iter keeps wait counting exact

        if ((g & 7) == 7) {
            // ---- epilogue for n-tile nt = g>>3
            const int nBase = (g >> 3) * 128;
#pragma unroll
            for (int mt = 0; mt < 4; mt++) {
#pragma unroll
                for (int jt = 0; jt < 8; jt++) {
                    int col = nBase + wn * 64 + jt * 8 + (tig << 1);
                    float b0 = bias[col], b1 = bias[col + 1];
                    size_t r0 = mBase + wm * 64 + mt * 16 + gid;
                    store2(C + r0 * Nc + col, acc[mt][jt][0] + b0, acc[mt][jt][1] + b1);
                    store2(C + (r0 + 8) * Nc + col, acc[mt][jt][2] + b0, acc[mt][jt][3] + b1);
#pragma unroll
                    for (int i = 0; i < 4; i++) acc[mt][jt][i] = 0.f;
                }
            }
        }
    }
}

// ---------------------------------------------------------------------------
// Tensor-core attention (unchanged): 1 CTA per window, warp = head.
// ---------------------------------------------------------------------------
__global__ void __launch_bounds__(256)
attn_mma_kernel(const __half* __restrict__ qkv, const __half* __restrict__ biash,
                __half* __restrict__ aout)
{
    extern __shared__ char sm[];
    uint32_t sbase;
    asm("{ .reg .u64 t; cvta.to.shared.u64 t, %1; cvt.u32.u64 %0, t; }"
        : "=r"(sbase) : "l"(sm));

    const int b    = blockIdx.x;
    const int t    = threadIdx.x;
    const int lane = t & 31;
    const int h    = t >> 5;
    const int gid  = lane >> 2;
    const int tig  = lane & 3;

    {
        const int r = t >> 2;
        const __half* src = qkv + ((size_t)b * 64 + r) * 768 + (t & 3) * 8;
        const uint32_t drow = sbase + r * 1536;
        const int rx = r & 7;
#pragma unroll
        for (int i = 0; i < 24; i++) {
            int cc = (t & 3) + (i << 2);
            cpasync16(drow + ((cc ^ rx) << 4), src + (i << 5));
        }
    }
    CP_COMMIT();
    CP_WAIT0();
    __syncthreads();

    uint32_t qA, kB, vB;
    {
        int r = ((lane >> 3) & 1) * 8 + (lane & 7);
        int ck = (h << 2) | (lane >> 4);
        qA = sbase + r * 1536 + ((ck ^ (r & 7)) << 4);
    }
    {
        int r = ((lane >> 4) << 3) + (lane & 7);
        int ck = ((8 + h) << 2) | ((lane >> 3) & 1);
        kB = sbase + r * 1536 + ((ck ^ (r & 7)) << 4);
    }
    {
        int tt = lane >> 3;
        int r = (tt & 1) * 8 + (lane & 7);
        int ck = ((16 + h) << 2) | (tt >> 1);
        vB = sbase + r * 1536 + ((ck ^ (r & 7)) << 4);
    }

    const float scale = 0.17677669529663687f;
    const __half* bia = biash + h * 4096;

#pragma unroll
    for (int h2 = 0; h2 < 2; h2++) {
        const int mt0 = h2 * 2;

        float sc[2][8][4];
#pragma unroll
        for (int mt = 0; mt < 2; mt++)
#pragma unroll
            for (int nt = 0; nt < 8; nt++)
#pragma unroll
                for (int i = 0; i < 4; i++) sc[mt][nt][i] = 0.f;

        unsigned kf[8][2][2];
#pragma unroll
        for (int ks = 0; ks < 2; ks++)
#pragma unroll
            for (int q = 0; q < 4; q++)
                ldsm4(kf[2 * q][ks][0], kf[2 * q][ks][1],
                      kf[2 * q + 1][ks][0], kf[2 * q + 1][ks][1],
                      (kB + q * 24576) ^ (ks << 5));
#pragma unroll
        for (int mt = 0; mt < 2; mt++)
#pragma unroll
            for (int ks = 0; ks < 2; ks++) {
                unsigned af[4];
                ldsm4(af[0], af[1], af[2], af[3],
                      (qA + (mt0 + mt) * 24576) ^ (ks << 5));
#pragma unroll
                for (int nt = 0; nt < 8; nt++)
                    mma_f16(sc[mt][nt], af, kf[nt][ks]);
            }

        float mx0[2], mx1[2];
#pragma unroll
        for (int mt = 0; mt < 2; mt++) {
            float m0 = -1e30f, m1 = -1e30f;
            int row = (mt0 + mt) * 16 + gid;
#pragma unroll
            for (int nt = 0; nt < 8; nt++) {
                float2 b0 = __half22float2(*(const __half2*)(bia + row * 64 + nt * 8 + 2 * tig));
                float2 b1 = __half22float2(*(const __half2*)(bia + (row + 8) * 64 + nt * 8 + 2 * tig));
                sc[mt][nt][0] = fmaf(sc[mt][nt][0], scale, b0.x);
                sc[mt][nt][1] = fmaf(sc[mt][nt][1], scale, b0.y);
                sc[mt][nt][2] = fmaf(sc[mt][nt][2], scale, b1.x);
                sc[mt][nt][3] = fmaf(sc[mt][nt][3], scale, b1.y);
                m0 = fmaxf(m0, fmaxf(sc[mt][nt][0], sc[mt][nt][1]));
                m1 = fmaxf(m1, fmaxf(sc[mt][nt][2], sc[mt][nt][3]));
            }
            m0 = fmaxf(m0, __shfl_xor_sync(0xffffffffu, m0, 1));
            m0 = fmaxf(m0, __shfl_xor_sync(0xffffffffu, m0, 2));
            m1 = fmaxf(m1, __shfl_xor_sync(0xffffffffu, m1, 1));
            m1 = fmaxf(m1, __shfl_xor_sync(0xffffffffu, m1, 2));
            mx0[mt] = m0; mx1[mt] = m1;
        }

        float s0[2], s1[2];
#pragma unroll
        for (int mt = 0; mt < 2; mt++) {
            float a0 = 0.f, a1 = 0.f;
#pragma unroll
            for (int nt = 0; nt < 8; nt++) {
                sc[mt][nt][0] = fexp(sc[mt][nt][0] - mx0[mt]); a0 += sc[mt][nt][0];
                sc[mt][nt][1] = fexp(sc[mt][nt][1] - mx0[mt]); a0 += sc[mt][nt][1];
                sc[mt][nt][2] = fexp(sc[mt][nt][2] - mx1[mt]); a1 += sc[mt][nt][2];
                sc[mt][nt][3] = fexp(sc[mt][nt][3] - mx1[mt]); a1 += sc[mt][nt][3];
            }
            a0 += __shfl_xor_sync(0xffffffffu, a0, 1);
            a0 += __shfl_xor_sync(0xffffffffu, a0, 2);
            a1 += __shfl_xor_sync(0xffffffffu, a1, 1);
            a1 += __shfl_xor_sync(0xffffffffu, a1, 2);
            s0[mt] = a0; s1[mt] = a1;
        }

        float pv[2][4][4];
#pragma unroll
        for (int mt = 0; mt < 2; mt++)
#pragma unroll
            for (int nt = 0; nt < 4; nt++)
#pragma unroll
                for (int i = 0; i < 4; i++) pv[mt][nt][i] = 0.f;

#pragma unroll
        for (int ks2 = 0; ks2 < 4; ks2++) {
            unsigned vb[4][2];
            uint32_t va = vB + ks2 * 24576;
            ldsm4t(vb[0][0], vb[0][1], vb[1][0], vb[1][1], va);
            ldsm4t(vb[2][0], vb[2][1], vb[3][0], vb[3][1], va ^ 32);
#pragma unroll
            for (int mt = 0; mt < 2; mt++) {
                unsigned pf[4];
                pf[0] = pack2(sc[mt][2 * ks2][0],     sc[mt][2 * ks2][1]);
                pf[1] = pack2(sc[mt][2 * ks2][2],     sc[mt][2 * ks2][3]);
                pf[2] = pack2(sc[mt][2 * ks2 + 1][0], sc[mt][2 * ks2 + 1][1]);
                pf[3] = pack2(sc[mt][2 * ks2 + 1][2], sc[mt][2 * ks2 + 1][3]);
#pragma unroll
                for (int nt = 0; nt < 4; nt++)
                    mma_f16(pv[mt][nt], pf, vb[nt]);
            }
        }

#pragma unroll
        for (int mt = 0; mt < 2; mt++) {
            float i0 = 1.f / s0[mt], i1 = 1.f / s1[mt];
            int row = (mt0 + mt) * 16 + gid;
            __half* o0 = aout + ((size_t)b * 64 + row) * 256 + h * 32 + 2 * tig;
            __half* o1 = o0 + 8 * 256;
#pragma unroll
            for (int nt = 0; nt < 4; nt++) {
                *(__half2*)(o0 + nt * 8) =
                    __floats2half2_rn(pv[mt][nt][0] * i0, pv[mt][nt][1] * i0);
                *(__half2*)(o1 + nt * 8) =
                    __floats2half2_rn(pv[mt][nt][2] * i1, pv[mt][nt][3] * i1);
            }
        }
    }
}

// ---------------------------------------------------------------------------
extern "C" void kernel_launch(void* const* d_in, const int* in_sizes, int n_in,
                              void* d_out, int out_size)
{
    const float* x   = (const float*)d_in[0];
    const float* qw  = (const float*)d_in[1];
    const float* qb  = (const float*)d_in[2];
    const float* pw  = (const float*)d_in[3];
    const float* pb  = (const float*)d_in[4];
    const float* tab = (const float*)d_in[5];
    const int*   rpi = (const int*)d_in[6];
    float* out = (float*)d_out;

    __half *qkvh = nullptr, *aouth = nullptr, *wh = nullptr, *bh = nullptr;
    cudaGetSymbolAddress((void**)&qkvh,  g_qkvh);
    cudaGetSymbolAddress((void**)&aouth, g_aouth);
    cudaGetSymbolAddress((void**)&wh,    g_wh);
    cudaGetSymbolAddress((void**)&bh,    g_biash);

    const int gemmSmem = RB_OFF + 4 * RSTAGE;   // 98304 B
    cudaFuncSetAttribute((const void*)gemm_res_kernel<float, __half>,
                         cudaFuncAttributeMaxDynamicSharedMemorySize, gemmSmem);
    cudaFuncSetAttribute((const void*)gemm_res_kernel<__half, float>,
                         cudaFuncAttributeMaxDynamicSharedMemorySize, gemmSmem);
    const int attnSmem = 98304;
    cudaFuncSetAttribute((const void*)attn_mma_kernel,
                         cudaFuncAttributeMaxDynamicSharedMemorySize, attnSmem);

    // weight converts + bias table (tiny)
    f2h_kernel<<<192, 256>>>(qw, wh, 196608 / 4);
    f2h_kernel<<<64, 256>>>(pw, wh + 196608, 65536 / 4);
    bias_pre_kernel<<<16, 256>>>(tab, rpi, bh);

    // QKV projection (fused x fp32->fp16): [524288,256] @ [768,256]^T + b
    gemm_res_kernel<float, __half><<<4096, 128, gemmSmem>>>(x, wh, qb, qkvh, 768, 6);

    // Tensor-core windowed attention (fp16 io)
    attn_mma_kernel<<<8192, 256, attnSmem>>>(qkvh, bh, aouth);

    // Output projection: [524288,256] @ [256,256]^T + b -> fp32 out
    gemm_res_kernel<__half, float><<<4096, 128, gemmSmem>>>(aouth, wh + 196608, pb, out, 256, 2);
}